// round 2
// baseline (speedup 1.0000x reference)
#include <cuda_runtime.h>
#include <math.h>

// HG2Vec fused loss, single persistent kernel.
// Decomposition: warp per (position, c-half). 4 warps/block = 2 positions/iter.
//  - per-lane float4 d-partition (75 float4/row), 35 register accumulators
//  - 32-bit byte offsets instead of 64-bit pointers (register diet)
//  - grid-stride persistence (592 blocks) -> no wave-transition overhead
//  - last-block-done deterministic reduction (fixed-order), counter self-resets
//    so the kernel is graph-replayable.

#define DIM       300
#define ROWBYTES  1200u          // 300 * 4
#define NPOS      16384          // B*L
#define NPAIRS    8192           // 2 positions per block-iteration
#define GRID      592            // 148 SMs * 4
#define THREADS   128            // 4 warps: 2 positions, 2 c-halves each

__device__ float        g_partial[GRID];
__device__ unsigned int g_ticket = 0;

__global__ __launch_bounds__(THREADS) void hg2vec_fused(
    const int*   __restrict__ pos_u,
    const int*   __restrict__ pos_v,
    const int*   __restrict__ info_v,
    const float* __restrict__ W_in,
    const float* __restrict__ W_out,
    const float* __restrict__ cmask,
    const float* __restrict__ sig_mask,
    const float* __restrict__ score_mask,
    float*       __restrict__ out)
{
    __shared__ float red[4][36];
    __shared__ float wloss[4];
    __shared__ bool  amLast;

    const int w    = threadIdx.x >> 5;     // 0..3
    const int lane = threadIdx.x & 31;
    const int grp  = w & 1;                // c-half
    const int wpos = w >> 1;               // which of the 2 positions in this block-iter

    const char* __restrict__ Win_b  = (const char*)W_in;
    const char* __restrict__ Wout_b = (const char*)W_out;

    // preload this warp's 5 context-mask values (uniform per warp)
    float cm[5];
#pragma unroll
    for (int c = 0; c < 5; c++) cm[c] = cmask[grp * 5 + c];

    float acc_loss = 0.f;

    for (int pp = blockIdx.x; pp < NPAIRS; pp += GRID) {
        const int p = pp * 2 + wpos;       // position 0..16383

        // ---- gather indices -> 32-bit byte offsets ----
        const unsigned puo = (unsigned)pos_u[p] * ROWBYTES;
        unsigned pvo[5], ivo[6];
#pragma unroll
        for (int c = 0; c < 5; c++)
            pvo[c] = (unsigned)pos_v[p * 10 + grp * 5 + c] * ROWBYTES;
#pragma unroll
        for (int i = 0; i < 6; i++)
            ivo[i] = (unsigned)info_v[p * 6 + i] * ROWBYTES;

        // ---- 35 accumulators ----
        float sc[5] = {0.f, 0.f, 0.f, 0.f, 0.f};
        float ai[30];
#pragma unroll
        for (int k = 0; k < 30; k++) ai[k] = 0.f;

#pragma unroll
        for (int jj = 0; jj < 3; jj++) {
            const int j = lane + jj * 32;
            if (j < 75) {
                const unsigned jb = (unsigned)j * 16u;
                const float4 t4 = *(const float4*)(Wout_b + puo + jb);
                float4 f4[6];
#pragma unroll
                for (int i = 0; i < 6; i++)
                    f4[i] = *(const float4*)(Win_b + ivo[i] + jb);
#pragma unroll
                for (int c = 0; c < 5; c++) {
                    const float4 a = *(const float4*)(Win_b + pvo[c] + jb);
                    sc[c] += a.x * t4.x + a.y * t4.y + a.z * t4.z + a.w * t4.w;
                    const float4 b = *(const float4*)(Wout_b + pvo[c] + jb);
#pragma unroll
                    for (int i = 0; i < 6; i++) {
                        ai[c * 6 + i] += b.x * f4[i].x + b.y * f4[i].y
                                       + b.z * f4[i].z + b.w * f4[i].w;
                    }
                }
            }
        }

        // ---- butterfly reduce across warp ----
#pragma unroll
        for (int off = 16; off; off >>= 1) {
#pragma unroll
            for (int c = 0; c < 5; c++)
                sc[c] += __shfl_xor_sync(0xffffffffu, sc[c], off);
#pragma unroll
            for (int k = 0; k < 30; k++)
                ai[k] += __shfl_xor_sync(0xffffffffu, ai[k], off);
        }

        // ---- stage to smem, eval transcendentals warp-parallel ----
        if (lane == 0) {
#pragma unroll
            for (int c = 0; c < 5; c++) red[w][c] = sc[c] * cm[c];
#pragma unroll
            for (int k = 0; k < 30; k++) red[w][5 + k] = ai[k];
        }
        __syncwarp();

#pragma unroll
        for (int r = 0; r < 2; r++) {
            const int k = lane + r * 32;
            if (k < 35) {
                const float v = red[w][k];
                if (k < 5) {
                    const float x = fminf(fmaxf(v, -10.f), 10.f);
                    acc_loss += log1pf(expf(-x));
                } else {
                    const int i = (k - 5) % 6;
                    const float x = fminf(fmaxf(v, -10.f), 10.f) * sig_mask[i];
                    acc_loss += log1pf(expf(-x)) * score_mask[i];
                }
            }
        }
        __syncwarp();   // red[w] reused next iteration
    }

    // ---- block reduction ----
#pragma unroll
    for (int off = 16; off; off >>= 1)
        acc_loss += __shfl_xor_sync(0xffffffffu, acc_loss, off);
    if (lane == 0) wloss[w] = acc_loss;
    __syncthreads();

    if (threadIdx.x == 0) {
        float s = wloss[0] + wloss[1] + wloss[2] + wloss[3];
        g_partial[blockIdx.x] = s;
        __threadfence();
        unsigned t = atomicAdd(&g_ticket, 1u);
        amLast = (t == GRID - 1);
    }
    __syncthreads();

    // ---- last block: deterministic fixed-order final sum ----
    if (amLast) {
        __shared__ float fs[THREADS];
        float v = 0.f;
        // fixed per-thread order: t, t+128, t+256, ...
        for (int i = threadIdx.x; i < GRID; i += THREADS)
            v += __ldcg(&g_partial[i]);
        fs[threadIdx.x] = v;
        __syncthreads();
#pragma unroll
        for (int st = THREADS / 2; st; st >>= 1) {
            if (threadIdx.x < st) fs[threadIdx.x] += fs[threadIdx.x + st];
            __syncthreads();
        }
        if (threadIdx.x == 0) {
            out[0] = fs[0];
            g_ticket = 0;            // reset for next graph replay
            __threadfence();
        }
    }
}

extern "C" void kernel_launch(void* const* d_in, const int* in_sizes, int n_in,
                              void* d_out, int out_size)
{
    const int*   pos_u  = (const int*)  d_in[0];
    const int*   pos_v  = (const int*)  d_in[1];
    const int*   info_v = (const int*)  d_in[2];
    const float* W_in   = (const float*)d_in[3];
    const float* W_out  = (const float*)d_in[4];
    const float* cmask  = (const float*)d_in[5];
    const float* sigm   = (const float*)d_in[6];
    const float* smask  = (const float*)d_in[7];

    hg2vec_fused<<<GRID, THREADS>>>(pos_u, pos_v, info_v, W_in, W_out,
                                    cmask, sigm, smask, (float*)d_out);
}

// round 3
// speedup vs baseline: 1.6008x; 1.6008x over previous
#include <cuda_runtime.h>
#include <math.h>

// HG2Vec fused loss, single persistent kernel, v3.
// Decomposition: warp per (position, context-PAIR). 5 warps/block = 1 position.
//  - 14 register accumulators per warp (2 score + 12 info) -> low reg pressure
//  - __launch_bounds__(160, 4) => 4 CTAs/SM = 20 warps/SM resident
//  - grid = 592 = exactly 4 CTAs/SM: true single-wave persistence
//  - per-lane float4 d-partition (75 float4/row), coalesced 512B/warp/row
//  - duplicate tgt/info rows across the 5 warps of a position hit L1 (same CTA)
//  - last-block-done deterministic reduction, counter self-resets (graph-safe)

#define DIM       300
#define ROWBYTES  1200u
#define NPOS      16384          // B*L
#define GRID      592            // 148 SMs * 4 resident CTAs
#define THREADS   160            // 5 warps = 1 position (2 contexts per warp)

__device__ float        g_partial[GRID];
__device__ unsigned int g_ticket = 0;

__global__ __launch_bounds__(THREADS, 4) void hg2vec_fused(
    const int*   __restrict__ pos_u,
    const int*   __restrict__ pos_v,
    const int*   __restrict__ info_v,
    const float* __restrict__ W_in,
    const float* __restrict__ W_out,
    const float* __restrict__ cmask,
    const float* __restrict__ sig_mask,
    const float* __restrict__ score_mask,
    float*       __restrict__ out)
{
    __shared__ float red[5][16];
    __shared__ float wloss[5];
    __shared__ bool  amLast;

    const int w    = threadIdx.x >> 5;     // 0..4 : context pair
    const int lane = threadIdx.x & 31;

    const char* __restrict__ Win_b  = (const char*)W_in;
    const char* __restrict__ Wout_b = (const char*)W_out;

    // per-warp context masks (2 contexts)
    const float cm0 = cmask[w * 2 + 0];
    const float cm1 = cmask[w * 2 + 1];

    // per-lane transcendental coefficients for the 14 terms this warp owns:
    //   k 0..1  : score terms (sign=1, weight=1; cmask applied at staging)
    //   k 2..13 : info terms, i = (k-2)%6 -> sign=sig_mask[i], weight=score_mask[i]
    float t_sgn = 1.f, t_wt = 0.f;
    if (lane < 14) {
        if (lane < 2) { t_sgn = 1.f; t_wt = 1.f; }
        else {
            const int i = (lane - 2) % 6;
            t_sgn = sig_mask[i];
            t_wt  = score_mask[i];
        }
    }

    float acc_loss = 0.f;

    for (int p = blockIdx.x; p < NPOS; p += GRID) {
        // ---- gather indices -> 32-bit byte offsets ----
        const unsigned puo  = (unsigned)pos_u[p] * ROWBYTES;
        const unsigned pvo0 = (unsigned)pos_v[p * 10 + w * 2 + 0] * ROWBYTES;
        const unsigned pvo1 = (unsigned)pos_v[p * 10 + w * 2 + 1] * ROWBYTES;
        unsigned ivo[6];
#pragma unroll
        for (int i = 0; i < 6; i++)
            ivo[i] = (unsigned)info_v[p * 6 + i] * ROWBYTES;

        // ---- 14 accumulators ----
        float sc0 = 0.f, sc1 = 0.f;
        float ai[12];
#pragma unroll
        for (int k = 0; k < 12; k++) ai[k] = 0.f;

#pragma unroll
        for (int jj = 0; jj < 3; jj++) {
            const int j = lane + jj * 32;
            if (j < 75) {
                const unsigned jb = (unsigned)j * 16u;
                const float4 t4 = *(const float4*)(Wout_b + puo + jb);
                float4 f4[6];
#pragma unroll
                for (int i = 0; i < 6; i++)
                    f4[i] = *(const float4*)(Win_b + ivo[i] + jb);

                const float4 a0 = *(const float4*)(Win_b + pvo0 + jb);
                const float4 a1 = *(const float4*)(Win_b + pvo1 + jb);
                const float4 b0 = *(const float4*)(Wout_b + pvo0 + jb);
                const float4 b1 = *(const float4*)(Wout_b + pvo1 + jb);

                sc0 += a0.x * t4.x + a0.y * t4.y + a0.z * t4.z + a0.w * t4.w;
                sc1 += a1.x * t4.x + a1.y * t4.y + a1.z * t4.z + a1.w * t4.w;
#pragma unroll
                for (int i = 0; i < 6; i++) {
                    ai[i]     += b0.x * f4[i].x + b0.y * f4[i].y
                               + b0.z * f4[i].z + b0.w * f4[i].w;
                    ai[6 + i] += b1.x * f4[i].x + b1.y * f4[i].y
                               + b1.z * f4[i].z + b1.w * f4[i].w;
                }
            }
        }

        // ---- butterfly reduce 14 accumulators across warp ----
#pragma unroll
        for (int off = 16; off; off >>= 1) {
            sc0 += __shfl_xor_sync(0xffffffffu, sc0, off);
            sc1 += __shfl_xor_sync(0xffffffffu, sc1, off);
#pragma unroll
            for (int k = 0; k < 12; k++)
                ai[k] += __shfl_xor_sync(0xffffffffu, ai[k], off);
        }

        // ---- stage to smem, eval transcendentals warp-parallel ----
        if (lane == 0) {
            red[w][0] = sc0 * cm0;
            red[w][1] = sc1 * cm1;
#pragma unroll
            for (int k = 0; k < 12; k++) red[w][2 + k] = ai[k];
        }
        __syncwarp();

        if (lane < 14) {
            const float v = red[w][lane];
            const float x = fminf(fmaxf(v, -10.f), 10.f) * t_sgn;
            acc_loss += log1pf(expf(-x)) * t_wt;
        }
        __syncwarp();   // red[w] reused next iteration
    }

    // ---- block reduction ----
#pragma unroll
    for (int off = 16; off; off >>= 1)
        acc_loss += __shfl_xor_sync(0xffffffffu, acc_loss, off);
    if (lane == 0) wloss[w] = acc_loss;
    __syncthreads();

    if (threadIdx.x == 0) {
        float s = wloss[0] + wloss[1] + wloss[2] + wloss[3] + wloss[4];
        g_partial[blockIdx.x] = s;
        __threadfence();
        unsigned t = atomicAdd(&g_ticket, 1u);
        amLast = (t == GRID - 1);
    }
    __syncthreads();

    // ---- last block: deterministic fixed-order final sum ----
    if (amLast) {
        __shared__ float fs[THREADS];
        float v = 0.f;
        for (int i = threadIdx.x; i < GRID; i += THREADS)
            v += __ldcg(&g_partial[i]);
        fs[threadIdx.x] = v;
        __syncthreads();
#pragma unroll
        for (int st = 128; st; st >>= 1) {
            if (threadIdx.x < st && threadIdx.x + st < THREADS)
                fs[threadIdx.x] += fs[threadIdx.x + st];
            __syncthreads();
        }
        if (threadIdx.x == 0) {
            out[0] = fs[0];
            g_ticket = 0;            // reset for next graph replay
            __threadfence();
        }
    }
}

extern "C" void kernel_launch(void* const* d_in, const int* in_sizes, int n_in,
                              void* d_out, int out_size)
{
    const int*   pos_u  = (const int*)  d_in[0];
    const int*   pos_v  = (const int*)  d_in[1];
    const int*   info_v = (const int*)  d_in[2];
    const float* W_in   = (const float*)d_in[3];
    const float* W_out  = (const float*)d_in[4];
    const float* cmask  = (const float*)d_in[5];
    const float* sigm   = (const float*)d_in[6];
    const float* smask  = (const float*)d_in[7];

    hg2vec_fused<<<GRID, THREADS>>>(pos_u, pos_v, info_v, W_in, W_out,
                                    cmask, sigm, smask, (float*)d_out);
}